// round 7
// baseline (speedup 1.0000x reference)
#include <cuda_runtime.h>
#include <stdint.h>

// ChannelPair2D: out[p, k] = x[p, i_k] * x[p, j_k], (i,j) i<j row-major triu.
// C=64 -> 2016 pairs, 65536 pixels. HBM-write-bound (~504 MiB out).
//
// R7 = R2 geometry (outer pixel loop, block blasts one pixel's 8KB per iter,
// high occupancy) + baked sorted descriptor table + register-frugal hoisting:
// 32-bit shared addresses (1 reg each), forced 8 CTAs/SM.

#define C_CH  64
#define NPAIR 2016
#define NQ    504               // NPAIR/4 quads
#define TPB   256
#define PPB   8                 // pixels per block
#define PLANE (PPB * C_CH)      // floats per replica plane (512)

// ---------------- compile-time quad table (sorted fast-first) ----------------
struct Q4s  { unsigned x, y, z, w; };
struct QTab { Q4s v[2 * TPB]; };

constexpr int off_of(int i) { return i * (127 - i) / 2; }

constexpr QTab build_qtab() {
    QTab t{};
    for (int s = 0; s < 2 * TPB; ++s) {
        t.v[s].x = 0u; t.v[s].y = 0xFFFFFFFFu; t.v[s].z = 0u; t.v[s].w = 0u;
    }
    int nfast = 0;
    for (int q = 0; q < NQ; ++q) {
        int k = 4 * q, i = 0;
        while (off_of(i + 1) <= k) ++i;
        int j = i + 1 + (k - off_of(i));
        if (j + 3 <= 63) ++nfast;
    }
    int pf = 0, pb = nfast;
    for (int q = 0; q < NQ; ++q) {
        int k = 4 * q, i = 0;
        while (off_of(i + 1) <= k) ++i;
        int j = i + 1 + (k - off_of(i));
        if (j + 3 <= 63) {
            // fast: bit31 | xi byte-off [0:8) | shifted-vec byte-off [8:22)
            t.v[pf].x = 0x80000000u
                      | (unsigned)(i * 4)
                      | ((unsigned)(((j & 3) * PLANE + (j & ~3)) * 4) << 8);
            t.v[pf].y = (unsigned)q;
            ++pf;
        } else {
            // boundary: 8 byte-offsets packed into z,w
            unsigned b[8] = {0,0,0,0,0,0,0,0};
            int ii = i, jj = j;
            for (int e = 0; e < 4; ++e) {
                b[2*e]   = (unsigned)(ii * 4);
                b[2*e+1] = (unsigned)(jj * 4);
                ++jj; if (jj > 63) { ++ii; jj = ii + 1; }
            }
            t.v[pb].x = 0u;
            t.v[pb].y = (unsigned)q;
            t.v[pb].z = b[0] | (b[1] << 8) | (b[2] << 16) | (b[3] << 24);
            t.v[pb].w = b[4] | (b[5] << 8) | (b[6] << 16) | (b[7] << 24);
            ++pb;
        }
    }
    return t;
}

__device__ const QTab g_qtab = build_qtab();

// 32-bit shared-memory load helpers
__device__ __forceinline__ float lds_f32(unsigned a) {
    float v;
    asm volatile("ld.shared.f32 %0, [%1];" : "=f"(v) : "r"(a));
    return v;
}
__device__ __forceinline__ float4 lds_f32v4(unsigned a) {
    float4 v;
    asm volatile("ld.shared.v4.f32 {%0,%1,%2,%3}, [%4];"
                 : "=f"(v.x), "=f"(v.y), "=f"(v.z), "=f"(v.w) : "r"(a));
    return v;
}

// ---------------- kernel ----------------
__global__ __launch_bounds__(TPB, 8)
void channelpair_kernel(const float* __restrict__ x,
                        float* __restrict__ out,
                        int npix) {
    // Shifted replicas: plane s holds x_p[c+s]; fast path reads x[j..j+3] as
    // one aligned LDS.128 at plane j&3, col j&~3.
    __shared__ __align__(16) float Bf[4 * PLANE];   // 8 KB

    const int tid  = threadIdx.x;
    const int pix0 = blockIdx.x * PPB;

    // Descriptors (sorted fast-first), coalesced LDG.128, L2-resident.
    const uint4* qt = (const uint4*)g_qtab.v;
    const uint4 d0 = qt[tid];
    const uint4 d1 = qt[tid + TPB];

    // Plane 0: PPB*64 floats = 128 float4 loads (threads 0..127)
    if (tid < PPB * (C_CH / 4)) {
        const float4* src = (const float4*)(x + (size_t)pix0 * C_CH);
        const int pix = pix0 + tid / (C_CH / 4);
        ((float4*)Bf)[tid] = (pix < npix) ? src[tid] : make_float4(0.f, 0.f, 0.f, 0.f);
    }
    __syncthreads();

    // Replica planes 1..3 (conflict-free scalar copies, 6 per thread)
    for (int t = tid; t < 3 * PLANE; t += TPB) {
        const int r = t % PLANE;
        const int c = r & 63;
        int sc = c + (1 + t / PLANE);
        if (sc > 63) sc = 63;
        Bf[PLANE + t] = Bf[(r - c) + sc];
    }
    __syncthreads();

    // Hoisted 32-bit shared addresses (1 reg each).
    const unsigned sb0 = (unsigned)__cvta_generic_to_shared(Bf);
    unsigned xa0 = sb0 + (d0.x & 0xFFu);
    unsigned va0 = sb0 + ((d0.x >> 8) & 0x3FFFu);
    unsigned xa1 = sb0 + (d1.x & 0xFFu);
    unsigned va1 = sb0 + ((d1.x >> 8) & 0x3FFFu);
    unsigned sb  = sb0;

    const bool f0 = (d0.x >> 31) != 0;
    const bool f1 = (d1.x >> 31) != 0;
    const bool a1 = d1.y < NQ;                    // slot 0 always active
    float4* o0 = (float4*)out + (size_t)pix0 * NQ + d0.y;
    float4* o1 = (float4*)out + (size_t)pix0 * NQ + (a1 ? d1.y : 0u);

    const int rem = npix - pix0;
    const int pc  = rem >= PPB ? PPB : rem;

    // Outer pixel loop (R2 geometry): whole block writes one pixel's
    // contiguous 8 KB per iteration.
    #pragma unroll 1
    for (int p = 0; p < pc; ++p) {
        // ---- slot 0 (warps 0..7 all fast) ----
        if (f0) {
            const float  xi = lds_f32(xa0);
            const float4 v  = lds_f32v4(va0);
            float4 r;
            r.x = xi * v.x; r.y = xi * v.y; r.z = xi * v.z; r.w = xi * v.w;
            __stcs(o0, r);
        } else {
            const unsigned z = d0.z, w = d0.w;
            float4 r;
            r.x = lds_f32(sb + (z & 255u))         * lds_f32(sb + ((z >> 8) & 255u));
            r.y = lds_f32(sb + ((z >> 16) & 255u)) * lds_f32(sb + (z >> 24));
            r.z = lds_f32(sb + (w & 255u))         * lds_f32(sb + ((w >> 8) & 255u));
            r.w = lds_f32(sb + ((w >> 16) & 255u)) * lds_f32(sb + (w >> 24));
            __stcs(o0, r);
        }
        // ---- slot 1 (fast block, then boundary block, then inactive) ----
        if (f1) {
            const float  xi = lds_f32(xa1);
            const float4 v  = lds_f32v4(va1);
            float4 r;
            r.x = xi * v.x; r.y = xi * v.y; r.z = xi * v.z; r.w = xi * v.w;
            __stcs(o1, r);
        } else if (a1) {
            const unsigned z = d1.z, w = d1.w;
            float4 r;
            r.x = lds_f32(sb + (z & 255u))         * lds_f32(sb + ((z >> 8) & 255u));
            r.y = lds_f32(sb + ((z >> 16) & 255u)) * lds_f32(sb + (z >> 24));
            r.z = lds_f32(sb + (w & 255u))         * lds_f32(sb + ((w >> 8) & 255u));
            r.w = lds_f32(sb + ((w >> 16) & 255u)) * lds_f32(sb + (w >> 24));
            __stcs(o1, r);
        }
        // advance one pixel (32-bit adds + two pointer bumps)
        xa0 += 256; va0 += 256; xa1 += 256; va1 += 256; sb += 256;
        o0  += NQ;  o1  += NQ;
    }
}

extern "C" void kernel_launch(void* const* d_in, const int* in_sizes, int n_in,
                              void* d_out, int out_size) {
    const float* x = (const float*)d_in[0];
    float* out = (float*)d_out;

    const int npix = in_sizes[0] / C_CH;            // 65536
    const int nblk = (npix + PPB - 1) / PPB;        // 8192

    channelpair_kernel<<<nblk, TPB>>>(x, out, npix);
}

// round 9
// speedup vs baseline: 1.8058x; 1.8058x over previous
#include <cuda_runtime.h>
#include <stdint.h>

// ChannelPair2D: out[p, k] = x[p, i_k] * x[p, j_k], (i,j) i<j row-major triu.
// C=64 -> 2016 pairs, 65536 pixels. HBM-write-bound (~504 MiB out).
//
// R8 = R2's proven geometry verbatim (IDENTITY thread->quad mapping so every
// warp's stores are a contiguous 512B range; outer unroll-1 pixel loop; plain
// STG; short divergent arms) + baked UNSORTED descriptor table read once into
// registers (kills R2's per-block table build + per-iter table LDS/unpack).

#define C_CH  64
#define NPAIR 2016
#define NQ    504               // NPAIR/4 quads
#define TPB   256
#define PPB   8                 // pixels per block
#define PLANE (PPB * C_CH)      // floats per replica plane (512)

// ---------------- compile-time quad table (IDENTITY order: slot q = quad q) ----
struct Q4s  { unsigned x, y, z, w; };
struct QTab { Q4s v[2 * TPB]; };

constexpr int off_of(int i) { return i * (127 - i) / 2; }

constexpr QTab build_qtab() {
    QTab t{};
    for (int s = 0; s < 2 * TPB; ++s) {
        t.v[s].x = 0u; t.v[s].y = 0u; t.v[s].z = 0u; t.v[s].w = 0u;
    }
    for (int q = 0; q < NQ; ++q) {
        int k = 4 * q, i = 0;
        while (off_of(i + 1) <= k) ++i;
        int j = i + 1 + (k - off_of(i));

        if (j + 3 <= 63) {
            // fast: bit31 | xi float-idx [0:8) | shifted-vec float-idx [8:24)
            t.v[q].x = 0x80000000u
                     | (unsigned)i
                     | ((unsigned)((j & 3) * PLANE + (j & ~3)) << 8);
        } else {
            t.v[q].x = 0u;
        }
        // 8 channel indices packed into z,w (used by boundary arm)
        unsigned b[8] = {0,0,0,0,0,0,0,0};
        int ii = i, jj = j;
        for (int e = 0; e < 4; ++e) {
            b[2*e]   = (unsigned)ii;
            b[2*e+1] = (unsigned)jj;
            ++jj; if (jj > 63) { ++ii; jj = ii + 1; }
        }
        t.v[q].z = b[0] | (b[1] << 8) | (b[2] << 16) | (b[3] << 24);
        t.v[q].w = b[4] | (b[5] << 8) | (b[6] << 16) | (b[7] << 24);
    }
    return t;
}

__device__ const QTab g_qtab = build_qtab();

// ---------------- kernel ----------------
__global__ __launch_bounds__(TPB)
void channelpair_kernel(const float* __restrict__ x,
                        float* __restrict__ out,
                        int npix) {
    // Shifted replicas: plane s holds x_p[c+s]; fast path reads x[j..j+3] as
    // one aligned LDS.128 at plane j&3, col j&~3.
    __shared__ __align__(16) float Bf[4 * PLANE];   // 8 KB

    const int tid  = threadIdx.x;
    const int pix0 = blockIdx.x * PPB;

    // Thread's two quads: q0 = tid (always < NQ), q1 = tid + 256 (may be >= NQ).
    // Coalesced LDG.128 of descriptors; L2-resident after first blocks.
    const uint4* qt = (const uint4*)g_qtab.v;
    const uint4 d0 = qt[tid];
    const uint4 d1 = qt[tid + TPB];
    const bool  a1 = (tid + TPB) < NQ;

    // Plane 0: PPB*64 floats = 128 float4 loads (threads 0..127)
    if (tid < PPB * (C_CH / 4)) {
        const float4* src = (const float4*)(x + (size_t)pix0 * C_CH);
        const int pix = pix0 + tid / (C_CH / 4);
        ((float4*)Bf)[tid] = (pix < npix) ? src[tid] : make_float4(0.f, 0.f, 0.f, 0.f);
    }
    __syncthreads();

    // Replica planes 1..3 (conflict-free scalar copies, 6 per thread)
    for (int t = tid; t < 3 * PLANE; t += TPB) {
        const int r = t % PLANE;
        const int c = r & 63;
        int sc = c + (1 + t / PLANE);
        if (sc > 63) sc = 63;
        Bf[PLANE + t] = Bf[(r - c) + sc];
    }
    __syncthreads();

    // Decode once (cheap, register-resident).
    const bool     f0  = (d0.x >> 31) != 0;
    const bool     f1  = (d1.x >> 31) != 0;
    const int      xi0 = (int)(d0.x & 0xFFu);
    const int      sv0 = (int)((d0.x >> 8) & 0xFFFFu);
    const int      xi1 = (int)(d1.x & 0xFFu);
    const int      sv1 = (int)((d1.x >> 8) & 0xFFFFu);

    float4* o0 = (float4*)out + (size_t)pix0 * NQ + tid;
    float4* o1 = o0 + TPB;

    const int rem = npix - pix0;
    const int pc  = rem >= PPB ? PPB : rem;

    // Outer pixel loop (R2 geometry): whole block writes one pixel's
    // contiguous 8 KB per iteration; warp stores are contiguous 512B.
    #pragma unroll 1
    for (int p = 0; p < pc; ++p) {
        const int   off = p * C_CH;            // pixel offset within each plane
        const float* xv = Bf + off;            // plane-0 view for this pixel

        // ---- quad q0 = tid ----
        {
            float4 r;
            if (f0) {
                const float  xi = xv[xi0];
                const float4 v  = *(const float4*)(Bf + sv0 + off);
                r.x = xi * v.x; r.y = xi * v.y; r.z = xi * v.z; r.w = xi * v.w;
            } else {
                const unsigned z = d0.z, w = d0.w;
                r.x = xv[z & 255u]         * xv[(z >> 8) & 255u];
                r.y = xv[(z >> 16) & 255u] * xv[z >> 24];
                r.z = xv[w & 255u]         * xv[(w >> 8) & 255u];
                r.w = xv[(w >> 16) & 255u] * xv[w >> 24];
            }
            o0[(size_t)p * NQ] = r;
        }
        // ---- quad q1 = tid + 256 ----
        if (a1) {
            float4 r;
            if (f1) {
                const float  xi = xv[xi1];
                const float4 v  = *(const float4*)(Bf + sv1 + off);
                r.x = xi * v.x; r.y = xi * v.y; r.z = xi * v.z; r.w = xi * v.w;
            } else {
                const unsigned z = d1.z, w = d1.w;
                r.x = xv[z & 255u]         * xv[(z >> 8) & 255u];
                r.y = xv[(z >> 16) & 255u] * xv[z >> 24];
                r.z = xv[w & 255u]         * xv[(w >> 8) & 255u];
                r.w = xv[(w >> 16) & 255u] * xv[w >> 24];
            }
            o1[(size_t)p * NQ] = r;
        }
    }
}

extern "C" void kernel_launch(void* const* d_in, const int* in_sizes, int n_in,
                              void* d_out, int out_size) {
    const float* x = (const float*)d_in[0];
    float* out = (float*)d_out;

    const int npix = in_sizes[0] / C_CH;            // 65536
    const int nblk = (npix + PPB - 1) / PPB;        // 8192

    channelpair_kernel<<<nblk, TPB>>>(x, out, npix);
}